// round 1
// baseline (speedup 1.0000x reference)
#include <cuda_runtime.h>
#include <cuda_bf16.h>
#include <math.h>

// Problem shapes (fixed): B=4, S=2048, D=1024, H=1024
#define PB 4
#define PS 2048
#define PD 1024
#define PH 1024
#define PM (PB * PS)          // 8192 rows
#define EPSQ 1e-8f

// Scratch (static device arrays; allocation is forbidden)
__device__ float g_v[(size_t)PM * (3 * PH)];   // 8192 x 3072 (v = x W_in^T + b_in)
__device__ float g_q[(size_t)PM * (4 * PH)];   // 8192 x 4096 (quaternions, then states in-place)

// ---------------------------------------------------------------------------
// Quaternion helpers. float4 = (w, x, y, z)
// ---------------------------------------------------------------------------
__device__ __forceinline__ float4 qmul(float4 a, float4 b) {
    // Hamilton product a * b
    return make_float4(
        a.x * b.x - a.y * b.y - a.z * b.z - a.w * b.w,
        a.x * b.y + a.y * b.x + a.z * b.w - a.w * b.z,
        a.x * b.z - a.y * b.w + a.z * b.x + a.w * b.y,
        a.x * b.w + a.y * b.z - a.z * b.y + a.w * b.x);
}

__device__ __forceinline__ float4 qnorm(float4 a) {
    float n = sqrtf(a.x * a.x + a.y * a.y + a.z * a.z + a.w * a.w);
    float s = 1.0f / (n + EPSQ);
    return make_float4(a.x * s, a.y * s, a.z * s, a.w * s);
}

// ---------------------------------------------------------------------------
// SGEMM: C[M,N] = A[M,K] * B[N,K]^T + bias[N]
// A, B, C row-major. M%128==0, N%128==0, K%8==0 guaranteed.
// 128x128 block tile, 8x8 per thread, BK=8, double-buffered smem.
// ---------------------------------------------------------------------------
__global__ __launch_bounds__(256, 2)
void sgemm_nt_bias(const float* __restrict__ A, const float* __restrict__ B,
                   const float* __restrict__ bias, float* __restrict__ C,
                   int M, int N, int K) {
    __shared__ float As[2][8][128 + 4];
    __shared__ float Bs[2][8][128 + 4];

    const int tid = threadIdx.x;
    const int tx = tid & 15;        // 0..15  (N direction)
    const int ty = tid >> 4;        // 0..15  (M direction)
    const int crow = blockIdx.y * 128;
    const int ccol = blockIdx.x * 128;

    const int lrow = tid >> 1;           // 0..127
    const int lcol = (tid & 1) << 2;     // 0 or 4

    const float* Ag = A + (size_t)(crow + lrow) * K + lcol;
    const float* Bg = B + (size_t)(ccol + lrow) * K + lcol;

    float acc[8][8];
#pragma unroll
    for (int i = 0; i < 8; i++)
#pragma unroll
        for (int j = 0; j < 8; j++) acc[i][j] = 0.0f;

    // prologue: stage tile 0
    {
        float4 a4 = *(const float4*)Ag;
        float4 b4 = *(const float4*)Bg;
        As[0][lcol + 0][lrow] = a4.x; As[0][lcol + 1][lrow] = a4.y;
        As[0][lcol + 2][lrow] = a4.z; As[0][lcol + 3][lrow] = a4.w;
        Bs[0][lcol + 0][lrow] = b4.x; Bs[0][lcol + 1][lrow] = b4.y;
        Bs[0][lcol + 2][lrow] = b4.z; Bs[0][lcol + 3][lrow] = b4.w;
    }
    __syncthreads();

    int buf = 0;
    for (int kt = 8; kt <= K; kt += 8) {
        const bool more = (kt < K);
        float4 a4n, b4n;
        if (more) {
            a4n = *(const float4*)(Ag + kt);
            b4n = *(const float4*)(Bg + kt);
        }
#pragma unroll
        for (int k = 0; k < 8; k++) {
            float af[8], bf[8];
            *(float4*)&af[0] = *(const float4*)&As[buf][k][ty * 8];
            *(float4*)&af[4] = *(const float4*)&As[buf][k][ty * 8 + 4];
            *(float4*)&bf[0] = *(const float4*)&Bs[buf][k][tx * 8];
            *(float4*)&bf[4] = *(const float4*)&Bs[buf][k][tx * 8 + 4];
#pragma unroll
            for (int i = 0; i < 8; i++)
#pragma unroll
                for (int j = 0; j < 8; j++)
                    acc[i][j] = fmaf(af[i], bf[j], acc[i][j]);
        }
        if (more) {
            buf ^= 1;
            As[buf][lcol + 0][lrow] = a4n.x; As[buf][lcol + 1][lrow] = a4n.y;
            As[buf][lcol + 2][lrow] = a4n.z; As[buf][lcol + 3][lrow] = a4n.w;
            Bs[buf][lcol + 0][lrow] = b4n.x; Bs[buf][lcol + 1][lrow] = b4n.y;
            Bs[buf][lcol + 2][lrow] = b4n.z; Bs[buf][lcol + 3][lrow] = b4n.w;
            __syncthreads();
        }
    }

    // epilogue: add bias, write out
    float bv[8];
#pragma unroll
    for (int j = 0; j < 8; j++) bv[j] = bias[ccol + tx * 8 + j];
#pragma unroll
    for (int i = 0; i < 8; i++) {
        float* Crow = C + (size_t)(crow + ty * 8 + i) * N + ccol + tx * 8;
        float4 o0, o1;
        o0.x = acc[i][0] + bv[0]; o0.y = acc[i][1] + bv[1];
        o0.z = acc[i][2] + bv[2]; o0.w = acc[i][3] + bv[3];
        o1.x = acc[i][4] + bv[4]; o1.y = acc[i][5] + bv[5];
        o1.z = acc[i][6] + bv[6]; o1.w = acc[i][7] + bv[7];
        *(float4*)(Crow + 0) = o0;
        *(float4*)(Crow + 4) = o1;
    }
}

// ---------------------------------------------------------------------------
// SU(2) exp map: v (M x 3H, row-major, grouped e = 3h+c) -> q (M x H x 4)
// ---------------------------------------------------------------------------
__global__ void qmap_kernel(const float* __restrict__ v, float* __restrict__ q) {
    int idx = blockIdx.x * blockDim.x + threadIdx.x;   // over M*H
    if (idx >= PM * PH) return;
    int m = idx >> 10;            // H = 1024
    int h = idx & 1023;
    const float* vp = v + (size_t)m * (3 * PH) + h * 3;
    float vx = vp[0], vy = vp[1], vz = vp[2];
    float th = sqrtf(vx * vx + vy * vy + vz * vz);
    float s, c;
    sincosf(th, &s, &c);
    float inv = s / (th + EPSQ);
    *(float4*)(q + (size_t)idx * 4) = make_float4(c, vx * inv, vy * inv, vz * inv);
}

// ---------------------------------------------------------------------------
// Parallel prefix product of quaternions along S, per (b, h) chain.
// One block per chain (grid = B*H = 4096). 256 threads x 8 elements.
// In-place: q buffer becomes normalized states (B,S,H,4).
// Also writes m_final (B,H,4).
// ---------------------------------------------------------------------------
__global__ __launch_bounds__(256)
void quat_scan_kernel(float* __restrict__ q, float* __restrict__ mfinal) {
    const int b = blockIdx.x >> 10;        // H = 1024
    const int h = blockIdx.x & 1023;
    const int t = threadIdx.x;

    // element offset of (b, s=0, h, 0); stride between s is H*4 = 4096 floats
    const size_t base = ((size_t)b * PS * PH + h) * 4;

    float4 loc[8];
#pragma unroll
    for (int j = 0; j < 8; j++)
        loc[j] = *(const float4*)(q + base + (size_t)(t * 8 + j) * (PH * 4));

    // thread-local aggregate: loc[7] * loc[6] * ... * loc[0]
    float4 agg = loc[0];
#pragma unroll
    for (int j = 1; j < 8; j++) agg = qmul(loc[j], agg);

    __shared__ float4 sbuf[256];
    sbuf[t] = agg;
    __syncthreads();

    // Hillis-Steele inclusive scan (noncommutative: later-index on the left)
#pragma unroll
    for (int d = 1; d < 256; d <<= 1) {
        float4 other;
        const bool has = (t >= d);
        if (has) other = sbuf[t - d];
        __syncthreads();
        if (has) sbuf[t] = qmul(sbuf[t], other);
        __syncthreads();
    }

    float4 p = make_float4(1.0f, 0.0f, 0.0f, 0.0f);
    if (t > 0) p = sbuf[t - 1];   // exclusive prefix = q_{t*8-1} ... q_0

#pragma unroll
    for (int j = 0; j < 8; j++) {
        p = qmul(loc[j], p);
        float4 outq = qnorm(p);
        *(float4*)(q + base + (size_t)(t * 8 + j) * (PH * 4)) = outq;
        if (t == 255 && j == 7)
            *(float4*)(mfinal + (size_t)blockIdx.x * 4) = outq;
    }
}

// ---------------------------------------------------------------------------
extern "C" void kernel_launch(void* const* d_in, const int* in_sizes, int n_in,
                              void* d_out, int out_size) {
    const float* x     = (const float*)d_in[0];   // (B,S,D)
    const float* W_in  = (const float*)d_in[1];   // (3H, D)
    const float* b_in  = (const float*)d_in[2];   // (3H)
    const float* W_out = (const float*)d_in[3];   // (D, 4H)
    const float* b_out = (const float*)d_in[4];   // (D)
    float* out = (float*)d_out;
    float* full_output = out;                              // (B,S,D)
    float* m_final     = out + (size_t)PM * PD;            // (B,H,4)

    float* v_ptr = nullptr;
    float* q_ptr = nullptr;
    cudaGetSymbolAddress((void**)&v_ptr, g_v);
    cudaGetSymbolAddress((void**)&q_ptr, g_q);

    // 1) v = x W_in^T + b_in   (M=8192, N=3072, K=1024)
    {
        dim3 grid(3 * PH / 128, PM / 128);
        sgemm_nt_bias<<<grid, 256>>>(x, W_in, b_in, v_ptr, PM, 3 * PH, PD);
    }
    // 2) exp map -> quaternions
    {
        int total = PM * PH;
        qmap_kernel<<<(total + 255) / 256, 256>>>(v_ptr, q_ptr);
    }
    // 3) prefix quaternion product (replaces the sequential scan) + m_final
    {
        quat_scan_kernel<<<PB * PH, 256>>>(q_ptr, m_final);
    }
    // 4) out = states W_out^T + b_out   (M=8192, N=1024, K=4096)
    {
        dim3 grid(PD / 128, PM / 128);
        sgemm_nt_bias<<<grid, 256>>>(q_ptr, W_out, b_out, full_output, PM, PD, 4 * PH);
    }
}